// round 5
// baseline (speedup 1.0000x reference)
#include <cuda_runtime.h>
#include <math.h>

// ---------------------------------------------------------------------------
// SelfAttention: out = softmax((Q K^T)/sqrt(Dh)) V  with fused QKV + out proj
// B=4, S=2048, D=1024, H=16, Dh=64.  kqv chunk order per reference: k, q, v.
// Round 5: cp.async 2-stage GEMM pipeline; 256-row flash-attn CTAs (halved
// KV L2 traffic), register-prefetched KV, exp2-domain softmax.
// ---------------------------------------------------------------------------

#define B_DIM 4
#define S_DIM 2048
#define D_DIM 1024
#define H_DIM 16
#define DH_DIM 64

__device__ float g_kqv[B_DIM * S_DIM * 3 * D_DIM];   // [B,S,3D]
__device__ float g_attn[B_DIM * S_DIM * D_DIM];      // [B,S,D]

// ---------------------------------------------------------------------------
__device__ __forceinline__ unsigned f2tf32(float f) {
    unsigned r;
    asm("cvt.rna.tf32.f32 %0, %1;" : "=r"(r) : "f"(f));
    return r;
}

__device__ __forceinline__ float exp2a(float x) {
    float r;
    asm("ex2.approx.f32 %0, %1;" : "=f"(r) : "f"(x));
    return r;
}

__device__ __forceinline__ void mma_tf32(float c[4],
                                         unsigned a0, unsigned a1, unsigned a2, unsigned a3,
                                         unsigned b0, unsigned b1)
{
    asm volatile(
        "mma.sync.aligned.m16n8k8.row.col.f32.tf32.tf32.f32 "
        "{%0,%1,%2,%3}, {%4,%5,%6,%7}, {%8,%9}, {%0,%1,%2,%3};"
        : "+f"(c[0]), "+f"(c[1]), "+f"(c[2]), "+f"(c[3])
        : "r"(a0), "r"(a1), "r"(a2), "r"(a3), "r"(b0), "r"(b1));
}

__device__ __forceinline__ void cp_async16(void* smem, const void* gmem) {
    unsigned saddr = (unsigned)__cvta_generic_to_shared(smem);
    asm volatile("cp.async.cg.shared.global [%0], [%1], 16;"
                 :: "r"(saddr), "l"(gmem));
}

// ---------------------------------------------------------------------------
// TF32 GEMM: C[M,N] = A[M,K] @ B[K,N] + bias[N]
// 128x128 CTA tile, BK=16, 2-stage cp.async pipeline, 8 warps, 64x32 warp
// tile. As [m][k] stride 20 (bank 4g+t bijective); Bs [k][n] stride 132
// (bank 4t+g injective). tf32 convert at fragment load.
// ---------------------------------------------------------------------------
__global__ void __launch_bounds__(256)
gemm_tf32_kernel(const float* __restrict__ A, const float* __restrict__ Bmat,
                 const float* __restrict__ bias, float* __restrict__ C,
                 int M, int N, int K)
{
    __shared__ float As[2][128][20];
    __shared__ float Bs[2][16][132];

    const int tid  = threadIdx.x;
    const int warp = tid >> 5;
    const int lane = tid & 31;
    const int row0 = blockIdx.y * 128;
    const int col0 = blockIdx.x * 128;

    const int wm = warp >> 2;          // 0..1
    const int wn = warp & 3;           // 0..3
    const int row_w = wm * 64;
    const int col_w = wn * 32;
    const int grp = lane >> 2;         // 0..7
    const int tig = lane & 3;          // 0..3

    // per-thread load coordinates (BK=16: 2 x 16B for A, 2 for B)
    const int a_r0 = tid >> 2;                  // 0..63   (i=0)
    const int a_kc = (tid & 3) << 2;            // 0,4,8,12
    const int b_k0 = tid >> 5;                  // 0..7    (i=0)
    const int b_nc = (tid & 31) << 2;           // 0..124

    float acc[4][4][4];
    #pragma unroll
    for (int mt = 0; mt < 4; mt++)
        #pragma unroll
        for (int nt = 0; nt < 4; nt++)
            #pragma unroll
            for (int r = 0; r < 4; r++) acc[mt][nt][r] = 0.f;

    const int NT = K >> 4;   // 64

    // prologue: stage 0
    {
        cp_async16(&As[0][a_r0][a_kc],      &A[(size_t)(row0 + a_r0) * K + a_kc]);
        cp_async16(&As[0][a_r0 + 64][a_kc], &A[(size_t)(row0 + a_r0 + 64) * K + a_kc]);
        cp_async16(&Bs[0][b_k0][b_nc],      &Bmat[(size_t)b_k0 * N + col0 + b_nc]);
        cp_async16(&Bs[0][b_k0 + 8][b_nc],  &Bmat[(size_t)(b_k0 + 8) * N + col0 + b_nc]);
        asm volatile("cp.async.commit_group;");
    }

    for (int it = 0; it < NT; it++) {
        const int s = it & 1;
        if (it + 1 < NT) {
            const int k0 = (it + 1) << 4;
            const int sn = s ^ 1;
            cp_async16(&As[sn][a_r0][a_kc],      &A[(size_t)(row0 + a_r0) * K + k0 + a_kc]);
            cp_async16(&As[sn][a_r0 + 64][a_kc], &A[(size_t)(row0 + a_r0 + 64) * K + k0 + a_kc]);
            cp_async16(&Bs[sn][b_k0][b_nc],      &Bmat[(size_t)(k0 + b_k0) * N + col0 + b_nc]);
            cp_async16(&Bs[sn][b_k0 + 8][b_nc],  &Bmat[(size_t)(k0 + b_k0 + 8) * N + col0 + b_nc]);
            asm volatile("cp.async.commit_group;");
            asm volatile("cp.async.wait_group 1;");
        } else {
            asm volatile("cp.async.wait_group 0;");
        }
        __syncthreads();

        #pragma unroll
        for (int ks = 0; ks < 2; ks++) {
            const int kk = ks * 8;
            unsigned af[4][4];
            #pragma unroll
            for (int mt = 0; mt < 4; mt++) {
                int m = row_w + mt * 16;
                af[mt][0] = f2tf32(As[s][m + grp    ][kk + tig]);
                af[mt][1] = f2tf32(As[s][m + 8 + grp][kk + tig]);
                af[mt][2] = f2tf32(As[s][m + grp    ][kk + 4 + tig]);
                af[mt][3] = f2tf32(As[s][m + 8 + grp][kk + 4 + tig]);
            }
            unsigned bf[4][2];
            #pragma unroll
            for (int nt = 0; nt < 4; nt++) {
                int n = col_w + nt * 8;
                bf[nt][0] = f2tf32(Bs[s][kk + tig    ][n + grp]);
                bf[nt][1] = f2tf32(Bs[s][kk + 4 + tig][n + grp]);
            }
            #pragma unroll
            for (int mt = 0; mt < 4; mt++)
                #pragma unroll
                for (int nt = 0; nt < 4; nt++)
                    mma_tf32(acc[mt][nt],
                             af[mt][0], af[mt][1], af[mt][2], af[mt][3],
                             bf[nt][0], bf[nt][1]);
        }
        __syncthreads();
    }

    #pragma unroll
    for (int mt = 0; mt < 4; mt++) {
        #pragma unroll
        for (int nt = 0; nt < 4; nt++) {
            int m = row0 + row_w + mt * 16;
            int n = col0 + col_w + nt * 8 + tig * 2;
            float b0 = bias[n], b1 = bias[n + 1];
            float2 v0, v1;
            v0.x = acc[mt][nt][0] + b0; v0.y = acc[mt][nt][1] + b1;
            v1.x = acc[mt][nt][2] + b0; v1.y = acc[mt][nt][3] + b1;
            *(float2*)&C[(size_t)(m + grp) * N + n]     = v0;
            *(float2*)&C[(size_t)(m + 8 + grp) * N + n] = v1;
        }
    }
}

// ---------------------------------------------------------------------------
// Tensor-core flash attention. CTA: 256 q-rows of one (b,h), 8 warps, each
// warp owns 32 rows = two m16 groups. KV tiles of 32 keys, reg-prefetched.
// exp2-domain softmax (Q pre-scaled by 0.125*log2e).
// Kn stride 68 (bank 4g+t), Vs stride 72 (bank 8t+g), Ps stride 36 (4g+t).
// ---------------------------------------------------------------------------
__global__ void __launch_bounds__(256)
attn_tc_kernel(const float* __restrict__ kqv, float* __restrict__ out)
{
    __shared__ unsigned Kn[32][68];
    __shared__ unsigned Vs[32][72];
    __shared__ unsigned Ps[8][16][36];

    const int tid  = threadIdx.x;
    const int warp = tid >> 5;
    const int lane = tid & 31;
    const int grp  = lane >> 2;
    const int tig  = lane & 3;
    const int b    = blockIdx.z;
    const int h    = blockIdx.y;
    const int qrow0 = blockIdx.x * 256;
    const int D3   = 3 * D_DIM;
    const float qs = 0.125f * 1.4426950408889634f;   // scale * log2(e)

    // Q fragments for both m-groups (q chunk at +D)
    unsigned qa[2][8][4];
    #pragma unroll
    for (int mg = 0; mg < 2; mg++) {
        int rl = qrow0 + warp * 32 + mg * 16 + grp;
        const float* qlo = kqv + (size_t)(b * S_DIM + rl) * D3 + D_DIM + h * DH_DIM;
        const float* qhi = qlo + (size_t)8 * D3;
        #pragma unroll
        for (int ks = 0; ks < 8; ks++) {
            int c = ks * 8 + tig;
            qa[mg][ks][0] = f2tf32(qlo[c]     * qs);
            qa[mg][ks][1] = f2tf32(qhi[c]     * qs);
            qa[mg][ks][2] = f2tf32(qlo[c + 4] * qs);
            qa[mg][ks][3] = f2tf32(qhi[c + 4] * qs);
        }
    }

    float o[2][8][4];
    #pragma unroll
    for (int mg = 0; mg < 2; mg++)
        #pragma unroll
        for (int nt = 0; nt < 8; nt++)
            #pragma unroll
            for (int r = 0; r < 4; r++) o[mg][nt][r] = 0.f;

    float mx[2][2] = {{-1e30f, -1e30f}, {-1e30f, -1e30f}};
    float ls[2][2] = {{0.f, 0.f}, {0.f, 0.f}};

    // KV prefetch coordinates: 2 x 16B per thread for each of K, V
    const int kv_key0 = tid >> 4;            // 0..15 (i=0), +16 (i=1)
    const int kv_c4   = (tid & 15) << 2;     // 0..60

    float4 pk[2], pv[2];
    {
        size_t base0 = (size_t)(b * S_DIM + kv_key0) * D3 + h * DH_DIM + kv_c4;
        size_t base1 = (size_t)(b * S_DIM + kv_key0 + 16) * D3 + h * DH_DIM + kv_c4;
        pk[0] = *(const float4*)(kqv + base0);
        pv[0] = *(const float4*)(kqv + base0 + 2 * D_DIM);
        pk[1] = *(const float4*)(kqv + base1);
        pv[1] = *(const float4*)(kqv + base1 + 2 * D_DIM);
    }

    for (int t0 = 0; t0 < S_DIM; t0 += 32) {
        // commit prefetched tile to smem (tf32-converted)
        #pragma unroll
        for (int i = 0; i < 2; i++) {
            int key = kv_key0 + i * 16;
            uint4 tk, tv;
            tk.x = f2tf32(pk[i].x); tk.y = f2tf32(pk[i].y);
            tk.z = f2tf32(pk[i].z); tk.w = f2tf32(pk[i].w);
            tv.x = f2tf32(pv[i].x); tv.y = f2tf32(pv[i].y);
            tv.z = f2tf32(pv[i].z); tv.w = f2tf32(pv[i].w);
            *(uint4*)&Kn[key][kv_c4] = tk;
            *(uint4*)&Vs[key][kv_c4] = tv;
        }
        __syncthreads();

        // prefetch next tile (overlaps with compute)
        if (t0 + 32 < S_DIM) {
            size_t base0 = (size_t)(b * S_DIM + t0 + 32 + kv_key0) * D3 + h * DH_DIM + kv_c4;
            size_t base1 = base0 + (size_t)16 * D3;
            pk[0] = *(const float4*)(kqv + base0);
            pv[0] = *(const float4*)(kqv + base0 + 2 * D_DIM);
            pk[1] = *(const float4*)(kqv + base1);
            pv[1] = *(const float4*)(kqv + base1 + 2 * D_DIM);
        }

        #pragma unroll
        for (int mg = 0; mg < 2; mg++) {
            // S = Q K^T (16 rows x 32 keys)
            float s[4][4];
            #pragma unroll
            for (int nt = 0; nt < 4; nt++) {
                #pragma unroll
                for (int r = 0; r < 4; r++) s[nt][r] = 0.f;
                #pragma unroll
                for (int ks = 0; ks < 8; ks++) {
                    int kk = ks * 8;
                    unsigned b0 = Kn[nt * 8 + grp][kk + tig];
                    unsigned b1 = Kn[nt * 8 + grp][kk + 4 + tig];
                    mma_tf32(s[nt], qa[mg][ks][0], qa[mg][ks][1],
                             qa[mg][ks][2], qa[mg][ks][3], b0, b1);
                }
            }

            // row max + online rescale (rows grp -> lo, grp+8 -> hi)
            float rl = -1e30f, rh = -1e30f;
            #pragma unroll
            for (int nt = 0; nt < 4; nt++) {
                rl = fmaxf(rl, fmaxf(s[nt][0], s[nt][1]));
                rh = fmaxf(rh, fmaxf(s[nt][2], s[nt][3]));
            }
            rl = fmaxf(rl, __shfl_xor_sync(0xffffffffu, rl, 1));
            rl = fmaxf(rl, __shfl_xor_sync(0xffffffffu, rl, 2));
            rh = fmaxf(rh, __shfl_xor_sync(0xffffffffu, rh, 1));
            rh = fmaxf(rh, __shfl_xor_sync(0xffffffffu, rh, 2));

            float mnl = fmaxf(mx[mg][0], rl);
            float mnh = fmaxf(mx[mg][1], rh);
            float cl = exp2a(mx[mg][0] - mnl);
            float ch = exp2a(mx[mg][1] - mnh);
            mx[mg][0] = mnl; mx[mg][1] = mnh;
            ls[mg][0] *= cl; ls[mg][1] *= ch;
            #pragma unroll
            for (int nt = 0; nt < 8; nt++) {
                o[mg][nt][0] *= cl; o[mg][nt][1] *= cl;
                o[mg][nt][2] *= ch; o[mg][nt][3] *= ch;
            }

            // P = 2^(S - m); stage to Ps
            #pragma unroll
            for (int nt = 0; nt < 4; nt++) {
                float p0 = exp2a(s[nt][0] - mnl);
                float p1 = exp2a(s[nt][1] - mnl);
                float p2 = exp2a(s[nt][2] - mnh);
                float p3 = exp2a(s[nt][3] - mnh);
                ls[mg][0] += p0 + p1;
                ls[mg][1] += p2 + p3;
                int c = nt * 8 + tig * 2;
                Ps[warp][grp    ][c]     = f2tf32(p0);
                Ps[warp][grp    ][c + 1] = f2tf32(p1);
                Ps[warp][grp + 8][c]     = f2tf32(p2);
                Ps[warp][grp + 8][c + 1] = f2tf32(p3);
            }
            __syncwarp();

            // O += P V
            #pragma unroll
            for (int ks = 0; ks < 4; ks++) {
                int kk = ks * 8;
                unsigned a0 = Ps[warp][grp    ][kk + tig];
                unsigned a1 = Ps[warp][grp + 8][kk + tig];
                unsigned a2 = Ps[warp][grp    ][kk + 4 + tig];
                unsigned a3 = Ps[warp][grp + 8][kk + 4 + tig];
                #pragma unroll
                for (int nt = 0; nt < 8; nt++) {
                    unsigned b0 = Vs[kk + tig    ][nt * 8 + grp];
                    unsigned b1 = Vs[kk + 4 + tig][nt * 8 + grp];
                    mma_tf32(o[mg][nt], a0, a1, a2, a3, b0, b1);
                }
            }
            __syncwarp();
        }
        __syncthreads();
    }

    // normalize + write
    #pragma unroll
    for (int mg = 0; mg < 2; mg++) {
        float l0 = ls[mg][0], l1 = ls[mg][1];
        l0 += __shfl_xor_sync(0xffffffffu, l0, 1);
        l0 += __shfl_xor_sync(0xffffffffu, l0, 2);
        l1 += __shfl_xor_sync(0xffffffffu, l1, 1);
        l1 += __shfl_xor_sync(0xffffffffu, l1, 2);
        float inv0 = 1.f / l0, inv1 = 1.f / l1;

        int rl = qrow0 + warp * 32 + mg * 16 + grp;
        float* olo = out + (size_t)(b * S_DIM + rl) * D_DIM + h * DH_DIM;
        float* ohi = olo + (size_t)8 * D_DIM;
        #pragma unroll
        for (int nt = 0; nt < 8; nt++) {
            int c = nt * 8 + tig * 2;
            float2 vlo, vhi;
            vlo.x = o[mg][nt][0] * inv0; vlo.y = o[mg][nt][1] * inv0;
            vhi.x = o[mg][nt][2] * inv1; vhi.y = o[mg][nt][3] * inv1;
            *(float2*)(olo + c) = vlo;
            *(float2*)(ohi + c) = vhi;
        }
    }
}

// ---------------------------------------------------------------------------
extern "C" void kernel_launch(void* const* d_in, const int* in_sizes, int n_in,
                              void* d_out, int out_size)
{
    const float* x     = (const float*)d_in[0];   // [4,2048,1024]
    const float* w_in  = (const float*)d_in[1];   // [1024,3072]
    const float* b_in  = (const float*)d_in[2];   // [3072]
    const float* w_out = (const float*)d_in[3];   // [1024,1024]
    const float* b_out = (const float*)d_in[4];   // [1024]
    float* out = (float*)d_out;

    float *kqv, *attn;
    cudaGetSymbolAddress((void**)&kqv, g_kqv);
    cudaGetSymbolAddress((void**)&attn, g_attn);

    const int M = B_DIM * S_DIM;                  // 8192

    // 1) kqv = x @ w_in + b_in     [8192, 3072]
    {
        dim3 grid(3 * D_DIM / 128, M / 128);
        gemm_tf32_kernel<<<grid, 256>>>(x, w_in, b_in, kqv, M, 3 * D_DIM, D_DIM);
    }
    // 2) attention -> g_attn [B,S,D]
    {
        dim3 grid(S_DIM / 256, H_DIM, B_DIM);
        attn_tc_kernel<<<grid, 256>>>(kqv, attn);
    }
    // 3) out = attn @ w_out + b_out  [8192, 1024]
    {
        dim3 grid(D_DIM / 128, M / 128);
        gemm_tf32_kernel<<<grid, 256>>>(attn, w_out, b_out, out, M, D_DIM, D_DIM);
    }
}

// round 8
// speedup vs baseline: 1.2535x; 1.2535x over previous
#include <cuda_runtime.h>
#include <math.h>

// ---------------------------------------------------------------------------
// SelfAttention: out = softmax((Q K^T)/sqrt(Dh)) V  with fused QKV + out proj
// B=4, S=2048, D=1024, H=16, Dh=64.  kqv chunk order per reference: k, q, v.
// Round 6: tf32 rounding hoisted out of all mainloops (pre-rounded operands),
// BK=32 cp.async GEMM, 64-key double-buffered flash attention.
// ---------------------------------------------------------------------------

#define B_DIM 4
#define S_DIM 2048
#define D_DIM 1024
#define H_DIM 16
#define DH_DIM 64

__device__ float g_kqv[B_DIM * S_DIM * 3 * D_DIM];   // [B,S,3D] (tf32-rounded)
__device__ float g_attn[B_DIM * S_DIM * D_DIM];      // [B,S,D]  (tf32-rounded)
__device__ float g_x[B_DIM * S_DIM * D_DIM];         // x rounded
__device__ float g_win[D_DIM * 3 * D_DIM];           // w_in rounded
__device__ float g_wout[D_DIM * D_DIM];              // w_out rounded

// ---------------------------------------------------------------------------
__device__ __forceinline__ unsigned f2tf32(float f) {
    unsigned r;
    asm("cvt.rna.tf32.f32 %0, %1;" : "=r"(r) : "f"(f));
    return r;
}

__device__ __forceinline__ float exp2a(float x) {
    float r;
    asm("ex2.approx.f32 %0, %1;" : "=f"(r) : "f"(x));
    return r;
}

__device__ __forceinline__ void mma_tf32(float c[4],
                                         unsigned a0, unsigned a1, unsigned a2, unsigned a3,
                                         unsigned b0, unsigned b1)
{
    asm volatile(
        "mma.sync.aligned.m16n8k8.row.col.f32.tf32.tf32.f32 "
        "{%0,%1,%2,%3}, {%4,%5,%6,%7}, {%8,%9}, {%0,%1,%2,%3};"
        : "+f"(c[0]), "+f"(c[1]), "+f"(c[2]), "+f"(c[3])
        : "r"(a0), "r"(a1), "r"(a2), "r"(a3), "r"(b0), "r"(b1));
}

__device__ __forceinline__ void cp_async16(void* smem, const void* gmem) {
    unsigned saddr = (unsigned)__cvta_generic_to_shared(smem);
    asm volatile("cp.async.cg.shared.global [%0], [%1], 16;"
                 :: "r"(saddr), "l"(gmem));
}

// ---------------------------------------------------------------------------
// Elementwise tf32 rounding (prologue; fully DRAM-bound)
// ---------------------------------------------------------------------------
__global__ void round_tf32_kernel(const float* __restrict__ in,
                                  float* __restrict__ out, int n4)
{
    int i = blockIdx.x * blockDim.x + threadIdx.x;
    if (i < n4) {
        float4 v = ((const float4*)in)[i];
        v.x = __uint_as_float(f2tf32(v.x));
        v.y = __uint_as_float(f2tf32(v.y));
        v.z = __uint_as_float(f2tf32(v.z));
        v.w = __uint_as_float(f2tf32(v.w));
        ((float4*)out)[i] = v;
    }
}

// ---------------------------------------------------------------------------
// TF32 GEMM: C[M,N] = A[M,K] @ B[K,N] + bias[N].  A,B pre-rounded to tf32.
// 128x128 CTA tile, BK=32, 2-stage cp.async, 8 warps, 64x32 warp tile.
// As [m][k] stride 36 (bank 4g+t); Bs [k][n] stride 136 (bank 8t+g).
// ROUND: round the output to tf32 (for tensors consumed by later mma stages).
// ---------------------------------------------------------------------------
template<bool ROUND>
__global__ void __launch_bounds__(256, 2)
gemm_tt_kernel(const float* __restrict__ A, const float* __restrict__ Bmat,
               const float* __restrict__ bias, float* __restrict__ C,
               int M, int N, int K)
{
    __shared__ float As[2][128][36];
    __shared__ float Bs[2][32][136];

    const int tid  = threadIdx.x;
    const int warp = tid >> 5;
    const int lane = tid & 31;
    const int row0 = blockIdx.y * 128;
    const int col0 = blockIdx.x * 128;

    const int wm = warp >> 2;
    const int wn = warp & 3;
    const int row_w = wm * 64;
    const int col_w = wn * 32;
    const int grp = lane >> 2;
    const int tig = lane & 3;

    float acc[4][4][4];
    #pragma unroll
    for (int mt = 0; mt < 4; mt++)
        #pragma unroll
        for (int nt = 0; nt < 4; nt++)
            #pragma unroll
            for (int r = 0; r < 4; r++) acc[mt][nt][r] = 0.f;

    const int NT = K >> 5;   // K/32

    // per-thread staging coords: 4 x 16B for A, 4 for B per stage
    // A: lin = tid + 256i : m = lin>>3 (0..127), kc = (lin&7)<<2
    // B: lin = tid + 256i : k = lin>>5 (0..31),  nc = (lin&31)<<2
    auto stage = [&](int s, int k0) {
        #pragma unroll
        for (int i = 0; i < 4; i++) {
            int lin = tid + i * 256;
            int m   = lin >> 3;
            int kc  = (lin & 7) << 2;
            cp_async16(&As[s][m][kc], &A[(size_t)(row0 + m) * K + k0 + kc]);
        }
        #pragma unroll
        for (int i = 0; i < 4; i++) {
            int lin = tid + i * 256;
            int k   = lin >> 5;
            int nc  = (lin & 31) << 2;
            cp_async16(&Bs[s][k][nc], &Bmat[(size_t)(k0 + k) * N + col0 + nc]);
        }
        asm volatile("cp.async.commit_group;");
    };

    stage(0, 0);

    for (int it = 0; it < NT; it++) {
        const int s = it & 1;
        if (it + 1 < NT) {
            stage(s ^ 1, (it + 1) << 5);
            asm volatile("cp.async.wait_group 1;");
        } else {
            asm volatile("cp.async.wait_group 0;");
        }
        __syncthreads();

        #pragma unroll
        for (int ks = 0; ks < 4; ks++) {
            const int kk = ks * 8;
            unsigned af[4][4];
            #pragma unroll
            for (int mt = 0; mt < 4; mt++) {
                int m = row_w + mt * 16;
                af[mt][0] = __float_as_uint(As[s][m + grp    ][kk + tig]);
                af[mt][1] = __float_as_uint(As[s][m + 8 + grp][kk + tig]);
                af[mt][2] = __float_as_uint(As[s][m + grp    ][kk + 4 + tig]);
                af[mt][3] = __float_as_uint(As[s][m + 8 + grp][kk + 4 + tig]);
            }
            unsigned bf[4][2];
            #pragma unroll
            for (int nt = 0; nt < 4; nt++) {
                int n = col_w + nt * 8;
                bf[nt][0] = __float_as_uint(Bs[s][kk + tig    ][n + grp]);
                bf[nt][1] = __float_as_uint(Bs[s][kk + 4 + tig][n + grp]);
            }
            #pragma unroll
            for (int mt = 0; mt < 4; mt++)
                #pragma unroll
                for (int nt = 0; nt < 4; nt++)
                    mma_tf32(acc[mt][nt],
                             af[mt][0], af[mt][1], af[mt][2], af[mt][3],
                             bf[nt][0], bf[nt][1]);
        }
        __syncthreads();
    }

    #pragma unroll
    for (int mt = 0; mt < 4; mt++) {
        #pragma unroll
        for (int nt = 0; nt < 4; nt++) {
            int m = row0 + row_w + mt * 16;
            int n = col0 + col_w + nt * 8 + tig * 2;
            float b0 = bias[n], b1 = bias[n + 1];
            float v[4];
            v[0] = acc[mt][nt][0] + b0; v[1] = acc[mt][nt][1] + b1;
            v[2] = acc[mt][nt][2] + b0; v[3] = acc[mt][nt][3] + b1;
            if (ROUND) {
                #pragma unroll
                for (int r = 0; r < 4; r++) v[r] = __uint_as_float(f2tf32(v[r]));
            }
            float2 v0, v1;
            v0.x = v[0]; v0.y = v[1];
            v1.x = v[2]; v1.y = v[3];
            *(float2*)&C[(size_t)(m + grp) * N + n]     = v0;
            *(float2*)&C[(size_t)(m + 8 + grp) * N + n] = v1;
        }
    }
}

// ---------------------------------------------------------------------------
// Tensor-core flash attention. CTA: 128 q-rows of one (b,h), 8 warps x 16
// rows. KV tiles of 64 keys, 2-stage cp.async double buffer. kqv is already
// tf32-rounded, so no conversions in the loop. exp2-domain softmax.
// Kn stride 68 (bank 4g+t), Vs stride 72 (bank 8t+g), Ps stride 68 (4g+t).
// ---------------------------------------------------------------------------
__global__ void __launch_bounds__(256, 2)
attn_tc_kernel(const float* __restrict__ kqv, float* __restrict__ out)
{
    __shared__ float Kn[2][64][68];
    __shared__ float Vs[2][64][72];
    __shared__ unsigned Ps[8][16][68];

    const int tid  = threadIdx.x;
    const int warp = tid >> 5;
    const int lane = tid & 31;
    const int grp  = lane >> 2;
    const int tig  = lane & 3;
    const int b    = blockIdx.z;
    const int h    = blockIdx.y;
    const int qrow0 = blockIdx.x * 128;
    const int D3   = 3 * D_DIM;
    const float qs = 0.125f * 1.4426950408889634f;   // 1/sqrt(64) * log2(e)

    // Q fragments (q chunk at +D), scaled into exp2 domain
    unsigned qa[8][4];
    {
        int rl = qrow0 + warp * 16 + grp;
        const float* qlo = kqv + (size_t)(b * S_DIM + rl) * D3 + D_DIM + h * DH_DIM;
        const float* qhi = qlo + (size_t)8 * D3;
        #pragma unroll
        for (int ks = 0; ks < 8; ks++) {
            int c = ks * 8 + tig;
            qa[ks][0] = f2tf32(qlo[c]     * qs);
            qa[ks][1] = f2tf32(qhi[c]     * qs);
            qa[ks][2] = f2tf32(qlo[c + 4] * qs);
            qa[ks][3] = f2tf32(qhi[c + 4] * qs);
        }
    }

    float o[8][4];
    #pragma unroll
    for (int nt = 0; nt < 8; nt++)
        #pragma unroll
        for (int r = 0; r < 4; r++) o[nt][r] = 0.f;

    float m_lo = -1e30f, m_hi = -1e30f, l_lo = 0.f, l_hi = 0.f;

    // KV staging: per stage, K and V each 64x64 floats = 16KB.
    // lin = tid + 256i (i 0..3): key = lin>>4 (0..63), c = (lin&15)<<2.
    auto stage_kv = [&](int s, int t0) {
        #pragma unroll
        for (int i = 0; i < 4; i++) {
            int lin = tid + i * 256;
            int key = lin >> 4;
            int c   = (lin & 15) << 2;
            const float* src = kqv + (size_t)(b * S_DIM + t0 + key) * D3 + h * DH_DIM + c;
            cp_async16(&Kn[s][key][c], src);
            cp_async16(&Vs[s][key][c], src + 2 * D_DIM);
        }
        asm volatile("cp.async.commit_group;");
    };

    stage_kv(0, 0);

    const int NT = S_DIM / 64;    // 32 tiles
    for (int it = 0; it < NT; it++) {
        const int s = it & 1;
        if (it + 1 < NT) {
            stage_kv(s ^ 1, (it + 1) * 64);
            asm volatile("cp.async.wait_group 1;");
        } else {
            asm volatile("cp.async.wait_group 0;");
        }
        __syncthreads();

        // S = Q K^T : 16 rows x 64 keys
        float sc[8][4];
        #pragma unroll
        for (int nt = 0; nt < 8; nt++) {
            #pragma unroll
            for (int r = 0; r < 4; r++) sc[nt][r] = 0.f;
            #pragma unroll
            for (int ks = 0; ks < 8; ks++) {
                int kk = ks * 8;
                unsigned b0 = __float_as_uint(Kn[s][nt * 8 + grp][kk + tig]);
                unsigned b1 = __float_as_uint(Kn[s][nt * 8 + grp][kk + 4 + tig]);
                mma_tf32(sc[nt], qa[ks][0], qa[ks][1], qa[ks][2], qa[ks][3], b0, b1);
            }
        }

        // row max (rows grp -> lo, grp+8 -> hi) + quad reduce
        float rl = -1e30f, rh = -1e30f;
        #pragma unroll
        for (int nt = 0; nt < 8; nt++) {
            rl = fmaxf(rl, fmaxf(sc[nt][0], sc[nt][1]));
            rh = fmaxf(rh, fmaxf(sc[nt][2], sc[nt][3]));
        }
        rl = fmaxf(rl, __shfl_xor_sync(0xffffffffu, rl, 1));
        rl = fmaxf(rl, __shfl_xor_sync(0xffffffffu, rl, 2));
        rh = fmaxf(rh, __shfl_xor_sync(0xffffffffu, rh, 1));
        rh = fmaxf(rh, __shfl_xor_sync(0xffffffffu, rh, 2));

        float mnl = fmaxf(m_lo, rl);
        float mnh = fmaxf(m_hi, rh);
        float cl = exp2a(m_lo - mnl);
        float ch = exp2a(m_hi - mnh);
        m_lo = mnl; m_hi = mnh;
        l_lo *= cl; l_hi *= ch;
        #pragma unroll
        for (int nt = 0; nt < 8; nt++) {
            o[nt][0] *= cl; o[nt][1] *= cl;
            o[nt][2] *= ch; o[nt][3] *= ch;
        }

        // P = 2^(S - m), stage to Ps
        #pragma unroll
        for (int nt = 0; nt < 8; nt++) {
            float p0 = exp2a(sc[nt][0] - mnl);
            float p1 = exp2a(sc[nt][1] - mnl);
            float p2 = exp2a(sc[nt][2] - mnh);
            float p3 = exp2a(sc[nt][3] - mnh);
            l_lo += p0 + p1;
            l_hi += p2 + p3;
            int c = nt * 8 + tig * 2;
            Ps[warp][grp    ][c]     = f2tf32(p0);
            Ps[warp][grp    ][c + 1] = f2tf32(p1);
            Ps[warp][grp + 8][c]     = f2tf32(p2);
            Ps[warp][grp + 8][c + 1] = f2tf32(p3);
        }
        __syncwarp();

        // O += P V
        #pragma unroll
        for (int ks = 0; ks < 8; ks++) {
            int kk = ks * 8;
            unsigned a0 = Ps[warp][grp    ][kk + tig];
            unsigned a1 = Ps[warp][grp + 8][kk + tig];
            unsigned a2 = Ps[warp][grp    ][kk + 4 + tig];
            unsigned a3 = Ps[warp][grp + 8][kk + 4 + tig];
            #pragma unroll
            for (int nt = 0; nt < 8; nt++) {
                unsigned b0 = __float_as_uint(Vs[s][kk + tig    ][nt * 8 + grp]);
                unsigned b1 = __float_as_uint(Vs[s][kk + 4 + tig][nt * 8 + grp]);
                mma_tf32(o[nt], a0, a1, a2, a3, b0, b1);
            }
        }
        __syncthreads();
    }

    // normalize + write (rounded to tf32: consumed by out-proj mma)
    l_lo += __shfl_xor_sync(0xffffffffu, l_lo, 1);
    l_lo += __shfl_xor_sync(0xffffffffu, l_lo, 2);
    l_hi += __shfl_xor_sync(0xffffffffu, l_hi, 1);
    l_hi += __shfl_xor_sync(0xffffffffu, l_hi, 2);
    float inv0 = 1.f / l_lo, inv1 = 1.f / l_hi;

    int rl = qrow0 + warp * 16 + grp;
    float* olo = out + (size_t)(b * S_DIM + rl) * D_DIM + h * DH_DIM;
    float* ohi = olo + (size_t)8 * D_DIM;
    #pragma unroll
    for (int nt = 0; nt < 8; nt++) {
        int c = nt * 8 + tig * 2;
        float2 vlo, vhi;
        vlo.x = __uint_as_float(f2tf32(o[nt][0] * inv0));
        vlo.y = __uint_as_float(f2tf32(o[nt][1] * inv0));
        vhi.x = __uint_as_float(f2tf32(o[nt][2] * inv1));
        vhi.y = __uint_as_float(f2tf32(o[nt][3] * inv1));
        *(float2*)(olo + c) = vlo;
        *(float2*)(ohi + c) = vhi;
    }
}

// ---------------------------------------------------------------------------
extern "C" void kernel_launch(void* const* d_in, const int* in_sizes, int n_in,
                              void* d_out, int out_size)
{
    const float* x     = (const float*)d_in[0];   // [4,2048,1024]
    const float* w_in  = (const float*)d_in[1];   // [1024,3072]
    const float* b_in  = (const float*)d_in[2];   // [3072]
    const float* w_out = (const float*)d_in[3];   // [1024,1024]
    const float* b_out = (const float*)d_in[4];   // [1024]
    float* out = (float*)d_out;

    float *kqv, *attn, *xr, *winr, *woutr;
    cudaGetSymbolAddress((void**)&kqv,   g_kqv);
    cudaGetSymbolAddress((void**)&attn,  g_attn);
    cudaGetSymbolAddress((void**)&xr,    g_x);
    cudaGetSymbolAddress((void**)&winr,  g_win);
    cudaGetSymbolAddress((void**)&woutr, g_wout);

    const int M = B_DIM * S_DIM;                  // 8192

    // 0) round operands to tf32 once
    {
        int n4x = M * D_DIM / 4;
        round_tf32_kernel<<<(n4x + 255) / 256, 256>>>(x, xr, n4x);
        int n4w = D_DIM * 3 * D_DIM / 4;
        round_tf32_kernel<<<(n4w + 255) / 256, 256>>>(w_in, winr, n4w);
        int n4o = D_DIM * D_DIM / 4;
        round_tf32_kernel<<<(n4o + 255) / 256, 256>>>(w_out, woutr, n4o);
    }

    // 1) kqv = x @ w_in + b_in    [8192, 3072], output tf32-rounded
    {
        dim3 grid(3 * D_DIM / 128, M / 128);
        gemm_tt_kernel<true><<<grid, 256>>>(xr, winr, b_in, kqv, M, 3 * D_DIM, D_DIM);
    }
    // 2) attention -> g_attn [B,S,D], output tf32-rounded
    {
        dim3 grid(S_DIM / 128, H_DIM, B_DIM);
        attn_tc_kernel<<<grid, 256>>>(kqv, attn);
    }
    // 3) out = attn @ w_out + b_out  [8192, 1024], fp32 output
    {
        dim3 grid(D_DIM / 128, M / 128);
        gemm_tt_kernel<false><<<grid, 256>>>(attn, woutr, b_out, out, M, D_DIM, D_DIM);
    }
}